// round 10
// baseline (speedup 1.0000x reference)
#include <cuda_runtime.h>
#include <cstdint>

// Problem constants
#define C_IN   8
#define H_IN   32
#define W_IN   32
#define C_OUT  32
#define KSZ    4
#define STRIDE 2
#define PAD    1
#define HO     16
#define WO     16
#define IN_FEAT  (C_IN * H_IN * W_IN)     // 8192
#define OUT_FEAT (C_OUT * HO * WO)        // 8192
#define WMAT_ELEMS ((unsigned)OUT_FEAT * (unsigned)IN_FEAT)  // 67,108,864

// Output layout in d_out (float32):
//   [0 : 16384)                 out_bounds (lower 8192, upper 8192)
//   [16384 : +67108864)         W_mat [OUT_FEAT, IN_FEAT] row-major
//   [then : +8192)              bias_backsub
#define OFF_WMAT  16384u
#define OFF_BIASB (16384u + WMAT_ELEMS)

// Grid layout (bounds blocks FIRST — measured faster than tail placement):
//   blocks [0, BOUNDS_BLOCKS)            : interval-conv bounds
//   blocks [BOUNDS_BLOCKS, +WMAT_BLOCKS) : Toeplitz stores, 8 x STG.256/thread
#define BOUNDS_BLOCKS 128u
#define WMAT_BLOCKS   4096u   // 4096 blk * 256 thr * 64B*... = 64KB per block

// 256-bit streaming store (sm_100+): one STG.256 = 32B, halves store-issue
// count vs float4. Address must be 32B-aligned (guaranteed by layout).
__device__ __forceinline__ void stg256_cs(float* p, const float v[8]) {
    asm volatile(
        "st.global.cs.v8.f32 [%0], {%1, %2, %3, %4, %5, %6, %7, %8};"
        :: "l"(p), "f"(v[0]), "f"(v[1]), "f"(v[2]), "f"(v[3]),
                   "f"(v[4]), "f"(v[5]), "f"(v[6]), "f"(v[7])
        : "memory");
}

__global__ void __launch_bounds__(256) fused_kernel(
        const float* __restrict__ bounds,
        const float* __restrict__ weight,
        const float* __restrict__ bias,
        float* __restrict__ out) {
    unsigned bid = blockIdx.x;

    if (bid >= BOUNDS_BLOCKS) {
        // ------------------------------------------------------------------
        // Toeplitz stores. Block sb owns rows {2sb, 2sb+1} = 16384 floats.
        // Thread stores 8 x 32B. Per iteration it (0..7):
        //   e_local = it*2048 + tid*8
        //   row j   = it >> 2
        //   ci      = (it&3)*2 + (tid>>7)
        //   h       = (tid>>2)&31,  w = (tid&3)*8   (fixed per thread)
        // W_mat[r,c] = weight[co,ci,kh,kw], kh = h-(2ho-1), kw = w'-(2wo-1),
        // valid iff in [0,4); else 0.
        // ------------------------------------------------------------------
        unsigned sb  = bid - BOUNDS_BLOCKS;
        unsigned tid = threadIdx.x;
        int h = (int)((tid >> 2) & 31u);
        int w = (int)((tid & 3u) << 3);
        int cihalf = (int)(tid >> 7);          // 0 or 1: ci = (it&3)*2 + cihalf

        float* tile = out + OFF_WMAT + (size_t)sb * 16384u;

        int r0 = (int)(sb * 2u);
        int co = r0 >> 8;                      // rows 2sb, 2sb+1 share co
        const float* wco = weight + co * (C_IN * KSZ * KSZ);

        // Per-row terms (j = 0,1): kh offset and kw window start
        int khv[2];                            // kh*4 if valid, else -1
        int kwo[2];                            // kw0 = w - (2wo-1)
#pragma unroll
        for (int j = 0; j < 2; j++) {
            int r  = r0 + j;
            int ho = (r >> 4) & 15;
            int wo = r & 15;
            int kh = h - (ho * STRIDE - PAD);
            khv[j] = ((unsigned)kh < (unsigned)KSZ) ? kh * KSZ : -1;
            kwo[j] = w - (wo * STRIDE - PAD);
        }

#pragma unroll
        for (int it = 0; it < 8; it++) {
            int j  = it >> 2;
            int ci = ((it & 3) << 1) + cihalf;
            float v[8];
#pragma unroll
            for (int jj = 0; jj < 8; jj++) v[jj] = 0.0f;
            if (khv[j] >= 0) {
                const float* p = wco + ci * (KSZ * KSZ) + khv[j];
#pragma unroll
                for (int jj = 0; jj < 8; jj++) {
                    int kw = kwo[j] + jj;
                    if ((unsigned)kw < (unsigned)KSZ) v[jj] = __ldg(p + kw);
                }
            }
            stg256_cs(tile + it * 2048 + tid * 8, v);
        }
        return;
    }

    // ----------------------------------------------------------------------
    // Interval conv bounds + bias_backsub. One warp per 8 outputs.
    // Back-substituted bounds equal these exactly; tighten is a no-op.
    // ----------------------------------------------------------------------
    int warp = threadIdx.x >> 5;
    int lane = threadIdx.x & 31;
    int rbase = (int)(bid * 8u + warp) * 8;     // 128 blk * 8 warps * 8 r = 8192

    const float* l = bounds;                    // [8,32,32]
    const float* u = bounds + IN_FEAT;

#pragma unroll 2
    for (int k = 0; k < 8; k++) {
        int r  = rbase + k;
        int co = r >> 8;
        int ho = (r >> 4) & 15;
        int wo = r & 15;
        int h0 = ho * STRIDE - PAD;
        int w0 = wo * STRIDE - PAD;

        float lo = 0.0f, up = 0.0f;
#pragma unroll
        for (int j = 0; j < 4; j++) {
            int t  = lane + j * 32;             // tap: ci*16 + kh*4 + kw
            int ci = t >> 4;
            int kh = (t >> 2) & 3;
            int kw = t & 3;
            int h  = h0 + kh;
            int w  = w0 + kw;
            if ((unsigned)h < (unsigned)H_IN && (unsigned)w < (unsigned)W_IN) {
                float wt = __ldg(weight + (((co * C_IN + ci) * KSZ + kh) * KSZ + kw));
                int in_idx = (ci * H_IN + h) * W_IN + w;
                float lv = __ldg(l + in_idx);
                float uv = __ldg(u + in_idx);
                float wp = fmaxf(wt, 0.0f);
                float wm = fminf(wt, 0.0f);
                lo = fmaf(wp, lv, fmaf(wm, uv, lo));
                up = fmaf(wp, uv, fmaf(wm, lv, up));
            }
        }
#pragma unroll
        for (int off = 16; off > 0; off >>= 1) {
            lo += __shfl_xor_sync(0xFFFFFFFFu, lo, off);
            up += __shfl_xor_sync(0xFFFFFFFFu, up, off);
        }
        if (lane == 0) {
            float b = __ldg(bias + co);
            out[r]             = lo + b;     // lower
            out[OUT_FEAT + r]  = up + b;     // upper
            out[OFF_BIASB + r] = b;          // bias_backsub
        }
    }
}

extern "C" void kernel_launch(void* const* d_in, const int* in_sizes, int n_in,
                              void* d_out, int out_size) {
    const float* bounds = (const float*)d_in[0];  // [2,8,32,32]
    const float* weight = (const float*)d_in[1];  // [32,8,4,4]
    const float* bias   = (const float*)d_in[2];  // [32]
    // d_in[3] = assignment, unused.
    float* out = (float*)d_out;

    fused_kernel<<<BOUNDS_BLOCKS + WMAT_BLOCKS, 256>>>(bounds, weight, bias, out);
}

// round 11
// speedup vs baseline: 1.0224x; 1.0224x over previous
#include <cuda_runtime.h>
#include <cstdint>

// Problem constants
#define C_IN   8
#define H_IN   32
#define W_IN   32
#define C_OUT  32
#define KSZ    4
#define STRIDE 2
#define PAD    1
#define HO     16
#define WO     16
#define IN_FEAT  (C_IN * H_IN * W_IN)     // 8192
#define OUT_FEAT (C_OUT * HO * WO)        // 8192
#define WMAT_ELEMS ((unsigned)OUT_FEAT * (unsigned)IN_FEAT)  // 67,108,864

// Output layout in d_out (float32):
//   [0 : 16384)                 out_bounds (lower 8192, upper 8192)
//   [16384 : +67108864)         W_mat [OUT_FEAT, IN_FEAT] row-major
//   [then : +8192)              bias_backsub
#define OFF_WMAT  16384u
#define OFF_BIASB (16384u + WMAT_ELEMS)

// Grid layout (bounds blocks FIRST — measured faster than tail placement:
// the latency-bound bounds warps coexist with store waves during ramp-up
// instead of extending the kernel past the last store wave):
//   blocks [0, BOUNDS_BLOCKS)            : interval-conv bounds
//   blocks [BOUNDS_BLOCKS, +WMAT_BLOCKS) : Toeplitz stores, 16 float4/thread
#define BOUNDS_BLOCKS 128u
#define WMAT_BLOCKS   4096u   // 4096 blk * 256 thr * 16 f4 = 16,777,216 f4

__global__ void __launch_bounds__(256) fused_kernel(
        const float* __restrict__ bounds,
        const float* __restrict__ weight,
        const float* __restrict__ bias,
        float* __restrict__ out) {
    unsigned bid = blockIdx.x;

    if (bid >= BOUNDS_BLOCKS) {
        // ------------------------------------------------------------------
        // Toeplitz stores. Block sb owns rows {2sb, 2sb+1} (64KB contiguous).
        // Thread's column geometry is loop-invariant:
        //   c = (it&7)*1024 + tid*4  =>  ci = it&7, h = tid>>3, w = (tid&7)*4.
        // 16 independent __stcs STG.128 per thread (MLP=16; 268MB >> L2).
        // Measured chip floor: 268.4MB / 41.4us = 6.5TB/s effective streaming
        // write bandwidth (write-back L2 double-transit against the
        // path-independent LTS cap). Verified insensitive to store width,
        // grid shape, and cache policy across 10 kernel variants.
        // ------------------------------------------------------------------
        unsigned sb  = bid - BOUNDS_BLOCKS;
        unsigned tid = threadIdx.x;
        int h = (int)(tid >> 3);
        int w = (int)((tid & 7u) << 2);

        float4* dst = reinterpret_cast<float4*>(out + OFF_WMAT)
                      + (size_t)sb * 4096u + tid;

        int r0 = (int)(sb * 2u);
        int co = r0 >> 8;                  // rows 2sb, 2sb+1 share co
        const float* wco = weight + co * (C_IN * KSZ * KSZ);

        int  khv[2];                       // kh*4 if valid, else -1
        int  kwo[2];                       // kw0 offset
        unsigned m[2];                     // 4 validity bits for kw0+0..3
#pragma unroll
        for (int j = 0; j < 2; j++) {
            int r  = r0 + j;
            int ho = (r >> 4) & 15;
            int wo = r & 15;
            int kh  = h - (ho * STRIDE - PAD);
            int kw0 = w - (wo * STRIDE - PAD);
            khv[j] = ((unsigned)kh < (unsigned)KSZ) ? kh * KSZ : -1;
            kwo[j] = kw0;
            unsigned mm = 0;
#pragma unroll
            for (int jj = 0; jj < 4; jj++)
                if ((unsigned)(kw0 + jj) < (unsigned)KSZ) mm |= (1u << jj);
            m[j] = mm;
        }

#pragma unroll
        for (int it = 0; it < 16; it++) {
            int j  = it >> 3;
            int ci = it & 7;
            float4 v = make_float4(0.f, 0.f, 0.f, 0.f);
            if (khv[j] >= 0) {
                const float* p = wco + ci * (KSZ * KSZ) + khv[j] + kwo[j];
                if (m[j] & 1u) v.x = __ldg(p + 0);
                if (m[j] & 2u) v.y = __ldg(p + 1);
                if (m[j] & 4u) v.z = __ldg(p + 2);
                if (m[j] & 8u) v.w = __ldg(p + 3);
            }
            __stcs(dst + it * 256, v);
        }
        return;
    }

    // ----------------------------------------------------------------------
    // Interval conv bounds + bias_backsub. One warp per 8 outputs.
    // Back-substituted bounds equal the forward interval conv exactly
    // (the Toeplitz matrix IS the conv), so the reference's tighten step
    // is a no-op and we emit the conv result for both.
    // ----------------------------------------------------------------------
    int warp = threadIdx.x >> 5;
    int lane = threadIdx.x & 31;
    int rbase = (int)(bid * 8u + warp) * 8;     // 128 blk * 8 warps * 8 r = 8192

    const float* l = bounds;                    // [8,32,32]
    const float* u = bounds + IN_FEAT;

#pragma unroll 2
    for (int k = 0; k < 8; k++) {
        int r  = rbase + k;
        int co = r >> 8;
        int ho = (r >> 4) & 15;
        int wo = r & 15;
        int h0 = ho * STRIDE - PAD;
        int w0 = wo * STRIDE - PAD;

        float lo = 0.0f, up = 0.0f;
#pragma unroll
        for (int j = 0; j < 4; j++) {
            int t  = lane + j * 32;             // tap: ci*16 + kh*4 + kw
            int ci = t >> 4;
            int kh = (t >> 2) & 3;
            int kw = t & 3;
            int h  = h0 + kh;
            int w  = w0 + kw;
            if ((unsigned)h < (unsigned)H_IN && (unsigned)w < (unsigned)W_IN) {
                float wt = __ldg(weight + (((co * C_IN + ci) * KSZ + kh) * KSZ + kw));
                int in_idx = (ci * H_IN + h) * W_IN + w;
                float lv = __ldg(l + in_idx);
                float uv = __ldg(u + in_idx);
                float wp = fmaxf(wt, 0.0f);
                float wm = fminf(wt, 0.0f);
                lo = fmaf(wp, lv, fmaf(wm, uv, lo));
                up = fmaf(wp, uv, fmaf(wm, lv, up));
            }
        }
#pragma unroll
        for (int off = 16; off > 0; off >>= 1) {
            lo += __shfl_xor_sync(0xFFFFFFFFu, lo, off);
            up += __shfl_xor_sync(0xFFFFFFFFu, up, off);
        }
        if (lane == 0) {
            float b = __ldg(bias + co);
            out[r]             = lo + b;     // lower
            out[OUT_FEAT + r]  = up + b;     // upper
            out[OFF_BIASB + r] = b;          // bias_backsub
        }
    }
}

extern "C" void kernel_launch(void* const* d_in, const int* in_sizes, int n_in,
                              void* d_out, int out_size) {
    const float* bounds = (const float*)d_in[0];  // [2,8,32,32]
    const float* weight = (const float*)d_in[1];  // [32,8,4,4]
    const float* bias   = (const float*)d_in[2];  // [32]
    // d_in[3] = assignment, unused.
    float* out = (float*)d_out;

    fused_kernel<<<BOUNDS_BLOCKS + WMAT_BLOCKS, 256>>>(bounds, weight, bias, out);
}